// round 12
// baseline (speedup 1.0000x reference)
#include <cuda_runtime.h>
#include <cuda_bf16.h>
#include <math.h>

#define BB 8
#define TT 256
#define UU 65
#define UL 64
#define VV 1024
#define ND 320             // stored diagonals t+u in [0,319]
#define ST 66              // diag row stride (floats), even -> 8B-aligned float2
#define NEG_BIG (-1e30f)
#define LOG2E 1.4426950408889634f
#define LN2F  0.6931471805599453f

__device__ __align__(16) float g_blankD[BB * ND * ST];  // [b][t+u][u] = lp_blank*log2e
__device__ __align__(16) float g_labelD[BB * ND * ST];  // [b][t+u][u] = lp_label*log2e
__device__ float g_ll[BB];
__device__ int   g_done;

__device__ __forceinline__ float warpMax(float v) {
#pragma unroll
    for (int o = 16; o > 0; o >>= 1) v = fmaxf(v, __shfl_xor_sync(0xffffffffu, v, o));
    return v;
}
__device__ __forceinline__ float warpSum(float v) {
#pragma unroll
    for (int o = 16; o > 0; o >>= 1) v += __shfl_xor_sync(0xffffffffu, v, o);
    return v;
}
__device__ __forceinline__ float lae2(float a, float b) {   // logaddexp, log2 domain
    float m = fmaxf(a, b);
    float d = fminf(a, b) - m;
    float p, r;
    asm("ex2.approx.ftz.f32 %0, %1;" : "=f"(p) : "f"(d));
    float q = 1.f + p;
    asm("lg2.approx.ftz.f32 %0, %1;" : "=f"(r) : "f"(q));
    return m + r;
}

// ---------------- Kernel 1: warp-per-row logsumexp (R6 schedule, proven 85% DRAM),
// diag-major pre-scaled store (R8-proven layout) --------------------------------
__global__ void __launch_bounds__(256) lse_kernel(const float* __restrict__ acts,
                                                  const int* __restrict__ labels) {
    const int row  = blockIdx.x * 8 + (threadIdx.x >> 5);
    const int lane = threadIdx.x & 31;

    const int u  = row % UU;
    const int bt = row / UU;
    const int t  = bt % TT;
    const int b  = bt / TT;

    const float4* a4 = reinterpret_cast<const float4*>(acts + (size_t)row * VV);
    float4 v[8];
#pragma unroll
    for (int j = 0; j < 8; ++j) v[j] = a4[lane + 32 * j];

    float m = -INFINITY;
#pragma unroll
    for (int j = 0; j < 8; ++j)
        m = fmaxf(m, fmaxf(fmaxf(v[j].x, v[j].y), fmaxf(v[j].z, v[j].w)));
    m = warpMax(m);

    float s = 0.f;
#pragma unroll
    for (int j = 0; j < 8; ++j)
        s += __expf(v[j].x - m) + __expf(v[j].y - m) + __expf(v[j].z - m) + __expf(v[j].w - m);
    s = warpSum(s);
    const float lse = m + __logf(s);

    float lv = 0.f;
    if (u < UL) {
        const int lab = labels[b * UL + u];
        const int q = lab >> 2, c = lab & 3, jj = q >> 5;
        float cand = 0.f;
#pragma unroll
        for (int j = 0; j < 8; ++j) {
            if (j == jj) {
                float4 f = v[j];
                cand = (c == 0) ? f.x : (c == 1) ? f.y : (c == 2) ? f.z : f.w;
            }
        }
        lv = __shfl_sync(0xffffffffu, cand, q & 31);
    }
    if (lane == 0) {
        const size_t base = ((size_t)b * ND + (t + u)) * ST + u;
        g_blankD[base] = (v[0].x - lse) * LOG2E;
        if (u < UL) g_labelD[base] = (lv - lse) * LOG2E;
    }
}

struct Ops { float bx, by, b64, lx, lm1, l63; };

// ---------------- Kernel 2: 1 warp/batch wavefront, no smem, depth-3 prefetch,
// label shuffles at load time, pm shuffle moved off the critical path ----------
__global__ void __launch_bounds__(32) alpha_kernel(const int* __restrict__ act_lens,
                                                   const int* __restrict__ label_lens,
                                                   float* __restrict__ out) {
    const int lane = threadIdx.x & 31;
    const int b    = blockIdx.x;

    const int t_tgt = act_lens[b] - 1;
    const int u_tgt = label_lens[b];
    const int d_tgt = t_tgt + u_tgt;

    const float* BD = g_blankD + (size_t)b * ND * ST;
    const float* LD = g_labelD + (size_t)b * ND * ST;
    const int u0 = 2 * lane, u1 = u0 + 1;

    auto loadOps = [&](int d) {
        const int dd = min(d - 1, ND - 1);
        const float* bp = BD + (size_t)dd * ST;
        const float* lp = LD + (size_t)dd * ST;
        Ops o;
        const float2 bv = *reinterpret_cast<const float2*>(bp + u0);
        const float2 lv = *reinterpret_cast<const float2*>(lp + u0);
        o.bx = bv.x; o.by = bv.y; o.lx = lv.x;
        o.b64 = bp[64];
        const float ly = lv.y;
        o.lm1 = __shfl_up_sync(0xffffffffu, ly, 1);   // label[dd][u0-1] (lane0: dead, killed by pm)
        o.l63 = __shfl_sync(0xffffffffu, ly, 31);     // label[dd][63]
        return o;
    };

    float a0 = 0.f, a1 = 0.f, a2 = 0.f, tgt = 0.f;

    Ops oA = loadOps(1), oB = loadOps(2), oC = loadOps(3);
    float pmv = __shfl_up_sync(0xffffffffu, a1, 1);
    float pm  = (lane == 0) ? NEG_BIG : pmv;

#pragma unroll 2
    for (int d = 1; d <= TT + UU - 2; ++d) {           // 1..319
        Ops oD = loadOps(d + 3);                       // depth-3 prefetch (R8-proven)

        const int t0 = d - u0, t1 = t0 - 1, t2 = d - 64;

        const float bl0 = (t0 >= 1) ? oA.bx : NEG_BIG;
        const float n0  = lae2(a0 + bl0, pm + oA.lm1);

        const float bl1 = (t1 >= 1) ? oA.by : NEG_BIG;
        const float n1  = lae2(a1 + bl1, a0 + oA.lx);

        const float bl2 = (t2 >= 1) ? oA.b64 : NEG_BIG;
        const float n2  = lae2(a2 + bl2, a1 + oA.l63);

        a0 = (t0 >= 0 && t0 < TT) ? n0 : a0;
        a1 = (t1 >= 0 && t1 < TT) ? n1 : a1;
        a2 = (t2 >= 0 && t2 < TT) ? n2 : a2;

        const float pick = (u_tgt == u0) ? n0 : ((u_tgt == u1) ? n1 : n2);
        tgt = (d == d_tgt) ? pick : tgt;

        // shfl for NEXT diagonal issued at the tail: overlaps back-edge + loads
        pmv = __shfl_up_sync(0xffffffffu, a1, 1);
        pm  = (lane == 0) ? NEG_BIG : pmv;

        oA = oB; oB = oC; oC = oD;
    }

    const int owner = (u_tgt >= 64) ? 31 : (u_tgt >> 1);
    const float av = __shfl_sync(0xffffffffu, tgt, owner);
    if (lane == 0) {
        const float bl = BD[(size_t)d_tgt * ST + u_tgt];   // log2e-scaled
        g_ll[b] = (av + bl) * LN2F;
        __threadfence();
        const int old = atomicAdd(&g_done, 1);
        if (old == BB - 1) {                 // last CTA: deterministic finalize (R6-proven)
            __threadfence();
            float s = 0.f;
#pragma unroll
            for (int i = 0; i < BB; ++i) s += g_ll[i];
            out[0] = -s / (float)BB;
            g_done = 0;                      // reset for next graph replay
            __threadfence();
        }
    }
}

extern "C" void kernel_launch(void* const* d_in, const int* in_sizes, int n_in,
                              void* d_out, int out_size) {
    const float* acts       = (const float*)d_in[0];
    const int*   labels     = (const int*)d_in[1];
    const int*   act_lens   = (const int*)d_in[2];
    const int*   label_lens = (const int*)d_in[3];
    float* out = (float*)d_out;

    const int rows = BB * TT * UU;                 // 133120 = 8 warps * 16640 blocks
    lse_kernel<<<rows / 8, 256>>>(acts, labels);
    alpha_kernel<<<BB, 32>>>(act_lens, label_lens, out);
}